// round 4
// baseline (speedup 1.0000x reference)
#include <cuda_runtime.h>
#include <cstdint>

// HiddenMarkovModel: 100k independent 2-state chains, 500 steps, JAX threefry2x32
// (partitionable counter scheme) reproduced bit-exactly.
//
// Full 20-round threefry2x32 (5 groups of 4 rounds, key injection after each).
// Per (step i, particle n, state s): one threefry block at key=keys[i],
// counter (0, 2n+s); bits = x0^x1; flip iff (bits>>9) < ceil(thr * 2^23)
// (exact: jax uniform u == (bits>>9)*2^-23, thr*2^23 is an exact exponent scale).
//
// R3 micro-opts: ks2 precomputed per step in smem (saves 1 LOP3/hash);
// one-hot output emitted via 64-bit constant select.

__device__ __forceinline__ void tf2x32_full(uint32_t k0, uint32_t k1,
                                            uint32_t c0, uint32_t c1,
                                            uint32_t& o0, uint32_t& o1) {
    uint32_t ks2 = k0 ^ k1 ^ 0x1BD11BDAu;
    uint32_t x0 = c0 + k0;
    uint32_t x1 = c1 + k1;
#define TF_ROUND(R) { x0 += x1; x1 = __funnelshift_l(x1, x1, (R)); x1 ^= x0; }
    TF_ROUND(13) TF_ROUND(15) TF_ROUND(26) TF_ROUND(6)
    x0 += k1;  x1 += ks2 + 1u;
    TF_ROUND(17) TF_ROUND(29) TF_ROUND(16) TF_ROUND(24)
    x0 += ks2; x1 += k0 + 2u;
    TF_ROUND(13) TF_ROUND(15) TF_ROUND(26) TF_ROUND(6)
    x0 += k0;  x1 += k1 + 3u;
    TF_ROUND(17) TF_ROUND(29) TF_ROUND(16) TF_ROUND(24)
    x0 += k1;  x1 += ks2 + 4u;
    TF_ROUND(13) TF_ROUND(15) TF_ROUND(26) TF_ROUND(6)
    x0 += ks2; x1 += k0 + 5u;
#undef TF_ROUND
    o0 = x0; o1 = x1;
}

// Variant with ks2 supplied (precomputed once per step, from smem).
__device__ __forceinline__ uint32_t tf2x32_x(uint32_t k0, uint32_t k1,
                                             uint32_t ks2, uint32_t c1) {
    uint32_t x0 = k0;          // c0 == 0
    uint32_t x1 = c1 + k1;
#define TF_ROUND(R) { x0 += x1; x1 = __funnelshift_l(x1, x1, (R)); x1 ^= x0; }
    TF_ROUND(13) TF_ROUND(15) TF_ROUND(26) TF_ROUND(6)
    x0 += k1;  x1 += ks2 + 1u;
    TF_ROUND(17) TF_ROUND(29) TF_ROUND(16) TF_ROUND(24)
    x0 += ks2; x1 += k0 + 2u;
    TF_ROUND(13) TF_ROUND(15) TF_ROUND(26) TF_ROUND(6)
    x0 += k0;  x1 += k1 + 3u;
    TF_ROUND(17) TF_ROUND(29) TF_ROUND(16) TF_ROUND(24)
    x0 += k1;  x1 += ks2 + 4u;
    TF_ROUND(13) TF_ROUND(15) TF_ROUND(26) TF_ROUND(6)
    x0 += ks2; x1 += k0 + 5u;
#undef TF_ROUND
    return x0 ^ x1;           // jax random_bits folds the pair with xor
}

__device__ __forceinline__ float bits_to_unif(uint32_t b) {
    return __uint_as_float((b >> 9) | 0x3f800000u) - 1.0f;
}

#define TPB 64

__global__ __launch_bounds__(TPB)
void HiddenMarkovModel_kernel(const float* __restrict__ initial,
                              const int* __restrict__ seed_ptr,
                              unsigned long long* __restrict__ out,
                              int N, int frames) {
    __shared__ uint4 skeys[512];   // (k0, k1, ks2, pad) per step; frames <= 512

    const int tid = threadIdx.x;
    const uint32_t seed = (uint32_t)seed_ptr[0];

    // root key = (hi, lo) = (0, seed) for int32 seed >= 0
    const uint32_t K0 = 0u, K1 = seed;

    // kp, ks = split(root): key[i] = full TF(root, (0, i)) output pair
    uint32_t kp0, kp1, ks0, ks1;
    tf2x32_full(K0, K1, 0u, 0u, kp0, kp1);
    tf2x32_full(K0, K1, 0u, 1u, ks0, ks1);

    // p = uniform(kp, (), f32) * 0.001  (bits = x0^x1 at counter (0,0))
    uint32_t pa, pb;
    tf2x32_full(kp0, kp1, 0u, 0u, pa, pb);
    const float p = bits_to_unif(pa ^ pb) * 0.001f;

    // Integer thresholds: u < thr  <=>  (bits>>9) < ceil(thr * 2^23)
    const uint32_t ithr1 = (uint32_t)ceilf(p * 8388608.0f);      // state 1
    const uint32_t ithr0 = (uint32_t)ceilf(0.2f * 8388608.0f);   // state 0 (1677722)

    // per-step keys: keys[j] = TF(ks, (0, j)); ks2 precomputed
    for (int j = tid; j < frames; j += TPB) {
        uint32_t y0, y1;
        tf2x32_full(ks0, ks1, 0u, (uint32_t)j, y0, y1);
        skeys[j] = make_uint4(y0, y1, y0 ^ y1 ^ 0x1BD11BDAu, 0u);
    }
    __syncthreads();

    const int n = blockIdx.x * TPB + tid;
    if (n >= N) return;

    // initial one-hot [N,2]: state = 1 iff initial[n,1] set
    uint32_t s = (initial[2 * n + 1] > 0.5f) ? 1u : 0u;
    const uint32_t base = 2u * (uint32_t)n;

    // little-endian float2 patterns: state0 -> (1,0), state1 -> (0,1)
    const unsigned long long ONEHOT0 = 0x000000003F800000ULL;
    const unsigned long long ONEHOT1 = 0x3F80000000000000ULL;

    unsigned long long* __restrict__ wp = out + n;

#pragma unroll 1
    for (int i = 0; i < frames; ++i) {
        const uint4 k = skeys[i];
        const uint32_t bits9 = tf2x32_x(k.x, k.y, k.z, base + s) >> 9;
        const uint32_t thr = s ? ithr1 : ithr0;
        s ^= (bits9 < thr) ? 1u : 0u;

        *wp = s ? ONEHOT1 : ONEHOT0;   // coalesced STG.64, 512B/warp
        wp += N;
    }
}

extern "C" void kernel_launch(void* const* d_in, const int* in_sizes, int n_in,
                              void* d_out, int out_size) {
    const float* initial = (const float*)d_in[0];
    const int*   seed    = (const int*)d_in[1];
    const int N      = in_sizes[0] / 2;          // 100000
    const int frames = out_size / in_sizes[0];   // 500

    const int grid = (N + TPB - 1) / TPB;        // 1563 CTAs of 64 threads
    HiddenMarkovModel_kernel<<<grid, TPB>>>(initial, seed,
                                            (unsigned long long*)d_out,
                                            N, frames);
}

// round 6
// speedup vs baseline: 1.0726x; 1.0726x over previous
#include <cuda_runtime.h>
#include <cstdint>

// HiddenMarkovModel: 100k 2-state chains x 500 steps, JAX threefry2x32
// (partitionable counter scheme), bit-exact.
// R6: (a) threefry adds forced onto fma pipe via IMAD with opaque multiplier
// (R4 showed alu=71.4% vs fma=11.8%); (b) 2 particles/thread for 2x ILP on the
// serial round chain + shared key regs; (c) STG.128 paired stores; (d) TPB=32
// to minimize wave quantization (1563 single-warp CTAs -> ~4% tail).

#define MAX_FRAMES 512

// Per step: A = (k0, k1, ks2, ks2+1), B = (k0+2, k1+3, ks2+4, k0+5)
__device__ uint4    g_keysA[MAX_FRAMES];
__device__ uint4    g_keysB[MAX_FRAMES];
__device__ uint32_t g_thr[2];   // thresholds pre-shifted by 9: [state0, state1]
__device__ uint32_t g_one;      // runtime 1 (opaque to ptxas -> keeps IMAD)

__device__ __forceinline__ void tf2x32_full(uint32_t k0, uint32_t k1,
                                            uint32_t c0, uint32_t c1,
                                            uint32_t& o0, uint32_t& o1) {
    uint32_t ks2 = k0 ^ k1 ^ 0x1BD11BDAu;
    uint32_t x0 = c0 + k0;
    uint32_t x1 = c1 + k1;
#define TF_ROUND(R) { x0 += x1; x1 = __funnelshift_l(x1, x1, (R)); x1 ^= x0; }
    TF_ROUND(13) TF_ROUND(15) TF_ROUND(26) TF_ROUND(6)
    x0 += k1;  x1 += ks2 + 1u;
    TF_ROUND(17) TF_ROUND(29) TF_ROUND(16) TF_ROUND(24)
    x0 += ks2; x1 += k0 + 2u;
    TF_ROUND(13) TF_ROUND(15) TF_ROUND(26) TF_ROUND(6)
    x0 += k0;  x1 += k1 + 3u;
    TF_ROUND(17) TF_ROUND(29) TF_ROUND(16) TF_ROUND(24)
    x0 += k1;  x1 += ks2 + 4u;
    TF_ROUND(13) TF_ROUND(15) TF_ROUND(26) TF_ROUND(6)
    x0 += ks2; x1 += k0 + 5u;
#undef TF_ROUND
    o0 = x0; o1 = x1;
}

// ---------- setup kernel ----------
__global__ void hmm_setup_kernel(const int* __restrict__ seed_ptr, int frames) {
    const uint32_t seed = (uint32_t)seed_ptr[0];
    const uint32_t K0 = 0u, K1 = seed;       // root key (hi, lo)

    uint32_t kp0, kp1, ks0, ks1;
    tf2x32_full(K0, K1, 0u, 0u, kp0, kp1);   // kp
    tf2x32_full(K0, K1, 0u, 1u, ks0, ks1);   // ks

    const int j = threadIdx.x;
    if (j < frames) {
        uint32_t y0, y1;
        tf2x32_full(ks0, ks1, 0u, (uint32_t)j, y0, y1);   // keys[j]
        uint32_t ks2 = y0 ^ y1 ^ 0x1BD11BDAu;
        g_keysA[j] = make_uint4(y0, y1, ks2, ks2 + 1u);
        g_keysB[j] = make_uint4(y0 + 2u, y1 + 3u, ks2 + 4u, y0 + 5u);
    }

    if (j == 0) {
        uint32_t pa, pb;
        tf2x32_full(kp0, kp1, 0u, 0u, pa, pb);
        float u = __uint_as_float(((pa ^ pb) >> 9) | 0x3f800000u) - 1.0f;
        float p = u * 0.001f;
        // u < thr  <=>  (bits>>9) < ceil(thr*2^23)  <=>  bits < (ceil(..) << 9)
        g_thr[0] = ((uint32_t)ceilf(0.2f * 8388608.0f)) << 9;   // state 0
        g_thr[1] = ((uint32_t)ceilf(p    * 8388608.0f)) << 9;   // state 1
        g_one    = 1u;
    }
}

// ---------- main kernel: 2 particles per thread ----------
#define TPB 32

// add on the fma pipe: dst = a * one + b  (one == 1, opaque to ptxas)
#define FADD3(dst, a, b) \
    asm("mad.lo.u32 %0, %1, %2, %3;" : "=r"(dst) : "r"(a), "r"(one), "r"(b))

__global__ __launch_bounds__(TPB)
void HiddenMarkovModel_kernel(const float* __restrict__ initial,
                              unsigned long long* __restrict__ out,
                              int N, int frames) {
    const int t  = blockIdx.x * TPB + threadIdx.x;   // over N/2 pairs
    const int n0 = 2 * t;
    if (n0 >= N) return;

    const uint32_t one = g_one;            // runtime 1
    const uint32_t T0  = g_thr[0];
    const uint32_t T1  = g_thr[1];

    // initial one-hot [N,2] for particles n0, n0+1
    const float4 ini = *(const float4*)(initial + 2 * n0);
    uint32_t sA = (ini.y > 0.5f) ? 1u : 0u;
    uint32_t sB = (ini.w > 0.5f) ? 1u : 0u;
    const uint32_t baseA = 2u * (uint32_t)n0;        // counter base, chain A
    const uint32_t baseB = baseA + 2u;               // chain B

    uint4* __restrict__ wp = (uint4*)(out + n0);     // 16B-aligned (n0 even)
    const int stride16 = N >> 1;                     // uint4 elements per frame

#pragma unroll 1
    for (int i = 0; i < frames; ++i) {
        const uint4 qa = __ldg(&g_keysA[i]);   // k0, k1, ks2, ks2+1
        const uint4 qb = __ldg(&g_keysB[i]);   // k0+2, k1+3, ks2+4, k0+5

        // two independent hash chains, shared key registers
        uint32_t a0 = qa.x, b0 = qa.x;
        uint32_t a1, b1, cA, cB;
        FADD3(cA, sA, baseA);  FADD3(a1, cA, qa.y);
        FADD3(cB, sB, baseB);  FADD3(b1, cB, qa.y);

#define TF2(R) { FADD3(a0, a1, a0); FADD3(b0, b1, b0); \
                 a1 = __funnelshift_l(a1, a1, (R)); \
                 b1 = __funnelshift_l(b1, b1, (R)); \
                 a1 ^= a0; b1 ^= b0; }
#define INJ2(p0, p1) { FADD3(a0, (p0), a0); FADD3(b0, (p0), b0); \
                       FADD3(a1, (p1), a1); FADD3(b1, (p1), b1); }
        TF2(13) TF2(15) TF2(26) TF2(6)
        INJ2(qa.y, qa.w)                       // += k1, ks2+1
        TF2(17) TF2(29) TF2(16) TF2(24)
        INJ2(qa.z, qb.x)                       // += ks2, k0+2
        TF2(13) TF2(15) TF2(26) TF2(6)
        INJ2(qa.x, qb.y)                       // += k0, k1+3
        TF2(17) TF2(29) TF2(16) TF2(24)
        INJ2(qa.y, qb.z)                       // += k1, ks2+4
        TF2(13) TF2(15) TF2(26) TF2(6)
        INJ2(qa.z, qb.w)                       // += ks2, k0+5
#undef TF2
#undef INJ2

        const uint32_t bitsA = a0 ^ a1;
        const uint32_t bitsB = b0 ^ b1;
        sA ^= (bitsA < (sA ? T1 : T0)) ? 1u : 0u;
        sB ^= (bitsB < (sB ? T1 : T0)) ? 1u : 0u;

        uint4 o;
        o.x = sA ? 0u : 0x3F800000u;   o.y = sA ? 0x3F800000u : 0u;
        o.z = sB ? 0u : 0x3F800000u;   o.w = sB ? 0x3F800000u : 0u;
        *wp = o;                       // STG.128, coalesced
        wp += stride16;
    }
}

extern "C" void kernel_launch(void* const* d_in, const int* in_sizes, int n_in,
                              void* d_out, int out_size) {
    const float* initial = (const float*)d_in[0];
    const int*   seed    = (const int*)d_in[1];
    const int N      = in_sizes[0] / 2;          // 100000
    const int frames = out_size / in_sizes[0];   // 500

    hmm_setup_kernel<<<1, MAX_FRAMES>>>(seed, frames);

    const int pairs = (N + 1) / 2;               // 50000
    const int grid  = (pairs + TPB - 1) / TPB;   // 1563 single-warp CTAs
    HiddenMarkovModel_kernel<<<grid, TPB>>>(initial,
                                            (unsigned long long*)d_out,
                                            N, frames);
}

// round 7
// speedup vs baseline: 1.2319x; 1.1486x over previous
#include <cuda_runtime.h>
#include <cstdint>

// HiddenMarkovModel: 100k 2-state chains x 500 steps, JAX threefry2x32
// (partitionable counter scheme), bit-exact.
// R7: attack latency exposure (issue stuck at 57.5% across R4/R6):
//  - software-pipelined key loads (prefetch i+1 into regs)
//  - only ONE add on the s-critical path (x1 = (base+k1) + s)
//  - TPB=128 for uniform warp->SMSP balance (2.64 warps every SMSP)
//  - threshold + one-hot selects as IMADs (fma pipe) instead of SELs (alu)
// Keeps R6: adds on fma pipe via IMAD w/ opaque one; 2 particles/thread;
// STG.128; pre-shifted integer thresholds.

#define MAX_FRAMES 512

// Per step: A = (k0, k1, ks2, ks2+1), B = (k0+2, k1+3, ks2+4, k0+5)
__device__ uint4    g_keysA[MAX_FRAMES];
__device__ uint4    g_keysB[MAX_FRAMES];
__device__ uint32_t g_thr[2];   // thresholds pre-shifted by 9: [state0, state1]
__device__ uint32_t g_one;      // runtime 1 (opaque to ptxas -> keeps IMAD)

__device__ __forceinline__ void tf2x32_full(uint32_t k0, uint32_t k1,
                                            uint32_t c0, uint32_t c1,
                                            uint32_t& o0, uint32_t& o1) {
    uint32_t ks2 = k0 ^ k1 ^ 0x1BD11BDAu;
    uint32_t x0 = c0 + k0;
    uint32_t x1 = c1 + k1;
#define TF_ROUND(R) { x0 += x1; x1 = __funnelshift_l(x1, x1, (R)); x1 ^= x0; }
    TF_ROUND(13) TF_ROUND(15) TF_ROUND(26) TF_ROUND(6)
    x0 += k1;  x1 += ks2 + 1u;
    TF_ROUND(17) TF_ROUND(29) TF_ROUND(16) TF_ROUND(24)
    x0 += ks2; x1 += k0 + 2u;
    TF_ROUND(13) TF_ROUND(15) TF_ROUND(26) TF_ROUND(6)
    x0 += k0;  x1 += k1 + 3u;
    TF_ROUND(17) TF_ROUND(29) TF_ROUND(16) TF_ROUND(24)
    x0 += k1;  x1 += ks2 + 4u;
    TF_ROUND(13) TF_ROUND(15) TF_ROUND(26) TF_ROUND(6)
    x0 += ks2; x1 += k0 + 5u;
#undef TF_ROUND
    o0 = x0; o1 = x1;
}

// ---------- setup kernel ----------
__global__ void hmm_setup_kernel(const int* __restrict__ seed_ptr, int frames) {
    const uint32_t seed = (uint32_t)seed_ptr[0];
    const uint32_t K0 = 0u, K1 = seed;       // root key (hi, lo)

    uint32_t kp0, kp1, ks0, ks1;
    tf2x32_full(K0, K1, 0u, 0u, kp0, kp1);   // kp
    tf2x32_full(K0, K1, 0u, 1u, ks0, ks1);   // ks

    const int j = threadIdx.x;
    if (j < frames) {
        uint32_t y0, y1;
        tf2x32_full(ks0, ks1, 0u, (uint32_t)j, y0, y1);   // keys[j]
        uint32_t ks2 = y0 ^ y1 ^ 0x1BD11BDAu;
        g_keysA[j] = make_uint4(y0, y1, ks2, ks2 + 1u);
        g_keysB[j] = make_uint4(y0 + 2u, y1 + 3u, ks2 + 4u, y0 + 5u);
    }

    if (j == 0) {
        uint32_t pa, pb;
        tf2x32_full(kp0, kp1, 0u, 0u, pa, pb);
        float u = __uint_as_float(((pa ^ pb) >> 9) | 0x3f800000u) - 1.0f;
        float p = u * 0.001f;
        // u < thr  <=>  (bits>>9) < ceil(thr*2^23)  <=>  bits < (ceil(..) << 9)
        g_thr[0] = ((uint32_t)ceilf(0.2f * 8388608.0f)) << 9;   // state 0
        g_thr[1] = ((uint32_t)ceilf(p    * 8388608.0f)) << 9;   // state 1
        g_one    = 1u;
    }
}

// ---------- main kernel: 2 particles/thread, pipelined key loads ----------
#define TPB 128

// add on the fma pipe: dst = a * one + b  (one == 1, opaque to ptxas)
#define FADD3(dst, a, b) \
    asm("mad.lo.u32 %0, %1, %2, %3;" : "=r"(dst) : "r"(a), "r"(one), "r"(b))
// dst = a * b + c  (all regs) on fma pipe
#define FMAD(dst, a, b, c) \
    asm("mad.lo.u32 %0, %1, %2, %3;" : "=r"(dst) : "r"(a), "r"(b), "r"(c))

__global__ __launch_bounds__(TPB)
void HiddenMarkovModel_kernel(const float* __restrict__ initial,
                              unsigned long long* __restrict__ out,
                              int N, int frames) {
    const int t  = blockIdx.x * TPB + threadIdx.x;   // over N/2 pairs
    const int n0 = 2 * t;
    if (n0 >= N) return;

    const uint32_t one = g_one;            // runtime 1
    const uint32_t T0  = g_thr[0];
    const uint32_t T1  = g_thr[1];
    const uint32_t dT  = T1 - T0;          // thr = T0 + s*dT
    const uint32_t C   = 0x3F800000u;      // 1.0f bits
    const uint32_t nC  = 0u - C;           // -C (for o.x = s*(-C)+C)

    // initial one-hot [N,2] for particles n0, n0+1
    const float4 ini = *(const float4*)(initial + 2 * n0);
    uint32_t sA = (ini.y > 0.5f) ? 1u : 0u;
    uint32_t sB = (ini.w > 0.5f) ? 1u : 0u;
    const uint32_t baseA = 2u * (uint32_t)n0;        // counter base, chain A
    const uint32_t baseB = baseA + 2u;               // chain B

    uint4* __restrict__ wp = (uint4*)(out + n0);     // 16B-aligned (n0 even)
    const int stride16 = N >> 1;

    // software pipeline: keys for iteration i live in qa/qb
    uint4 qa = __ldg(&g_keysA[0]);
    uint4 qb = __ldg(&g_keysB[0]);

#pragma unroll 1
    for (int i = 0; i < frames; ++i) {
        // prefetch next iteration's keys (index i+1 < MAX_FRAMES always)
        const uint4 qa_n = __ldg(&g_keysA[i + 1]);
        const uint4 qb_n = __ldg(&g_keysB[i + 1]);

        // off the s-critical path: base + k1
        uint32_t cA0, cB0;
        FADD3(cA0, baseA, qa.y);
        FADD3(cB0, baseB, qa.y);

        // two independent hash chains; x1 = (base+k1) + s  (one add on s)
        uint32_t a0 = qa.x, b0 = qa.x;
        uint32_t a1, b1;
        FADD3(a1, sA, cA0);
        FADD3(b1, sB, cB0);

#define TF2(R) { FADD3(a0, a1, a0); FADD3(b0, b1, b0); \
                 a1 = __funnelshift_l(a1, a1, (R)); \
                 b1 = __funnelshift_l(b1, b1, (R)); \
                 a1 ^= a0; b1 ^= b0; }
#define INJ2(p0, p1) { FADD3(a0, (p0), a0); FADD3(b0, (p0), b0); \
                       FADD3(a1, (p1), a1); FADD3(b1, (p1), b1); }
        TF2(13) TF2(15) TF2(26) TF2(6)
        INJ2(qa.y, qa.w)                       // += k1, ks2+1
        TF2(17) TF2(29) TF2(16) TF2(24)
        INJ2(qa.z, qb.x)                       // += ks2, k0+2
        TF2(13) TF2(15) TF2(26) TF2(6)
        INJ2(qa.x, qb.y)                       // += k0, k1+3
        TF2(17) TF2(29) TF2(16) TF2(24)
        INJ2(qa.y, qb.z)                       // += k1, ks2+4
        TF2(13) TF2(15) TF2(26) TF2(6)
        INJ2(qa.z, qb.w)                       // += ks2, k0+5
#undef TF2
#undef INJ2

        const uint32_t bitsA = a0 ^ a1;
        const uint32_t bitsB = b0 ^ b1;

        uint32_t thrA, thrB;
        FMAD(thrA, sA, dT, T0);                // thr = T0 + s*dT  (fma pipe)
        FMAD(thrB, sB, dT, T0);
        sA ^= (bitsA < thrA) ? 1u : 0u;
        sB ^= (bitsB < thrB) ? 1u : 0u;

        // one-hot via IMAD (fma pipe): o.x = s*(-C)+C, o.y = s*C
        uint4 o;
        FMAD(o.x, sA, nC, C);
        FMAD(o.y, sA, C, 0u);
        FMAD(o.z, sB, nC, C);
        FMAD(o.w, sB, C, 0u);
        *wp = o;                               // STG.128, coalesced
        wp += stride16;

        qa = qa_n; qb = qb_n;                  // rotate pipeline
    }
}

extern "C" void kernel_launch(void* const* d_in, const int* in_sizes, int n_in,
                              void* d_out, int out_size) {
    const float* initial = (const float*)d_in[0];
    const int*   seed    = (const int*)d_in[1];
    const int N      = in_sizes[0] / 2;          // 100000
    const int frames = out_size / in_sizes[0];   // 500

    hmm_setup_kernel<<<1, MAX_FRAMES>>>(seed, frames);

    const int pairs = (N + 1) / 2;               // 50000
    const int grid  = (pairs + TPB - 1) / TPB;   // 391 CTAs of 128 threads
    HiddenMarkovModel_kernel<<<grid, TPB>>>(initial,
                                            (unsigned long long*)d_out,
                                            N, frames);
}